// round 1
// baseline (speedup 1.0000x reference)
#include <cuda_runtime.h>

// Problem constants
#define Bb   2
#define Ss   2048
#define Dd   1024
#define Hh   16
#define DKh  64
#define Mtot (Bb * Ss)   // 4096

// Scratch (device globals; no allocations allowed)
__device__ float g_q[Mtot * Dd];
__device__ float g_k[Mtot * Dd];
__device__ float g_v[Mtot * Dd];
__device__ float g_o[Mtot * Dd];

// ---------------------------------------------------------------------------
// SGEMM with bias: C[M,N] = (A[M,K] * W[K,N] + bias[N]) * scale
// 128x128 block tile, BK=8, 256 threads, 8x8 micro-tile per thread.
// ---------------------------------------------------------------------------
#define BM 128
#define BN 128
#define BKK 8
#define TM 8
#define TN 8

__global__ __launch_bounds__(256) void sgemm_bias(
    const float* __restrict__ A, const float* __restrict__ W,
    const float* __restrict__ bias, float* __restrict__ C,
    int M, int N, int K, float scale)
{
    __shared__ float As[BKK * BM];   // transposed: As[k][m]
    __shared__ float Bs[BKK * BN];   // natural:    Bs[k][n]

    const int t  = threadIdx.x;
    const int tx = t & 15;          // 0..15 -> col group
    const int ty = t >> 4;          // 0..15 -> row group
    const int row0 = blockIdx.y * BM;
    const int col0 = blockIdx.x * BN;

    const int aRow = t >> 1;            // 0..127
    const int aCol = (t & 1) * 4;       // 0 or 4
    const int bRow = t >> 5;            // 0..7
    const int bCol = (t & 31) * 4;      // 0..124

    const float* Ap = A + (size_t)(row0 + aRow) * K + aCol;
    const float* Wp = W + (size_t)bRow * N + col0 + bCol;

    float acc[TM][TN];
#pragma unroll
    for (int i = 0; i < TM; i++)
#pragma unroll
        for (int j = 0; j < TN; j++) acc[i][j] = 0.f;

    for (int k0 = 0; k0 < K; k0 += BKK) {
        float4 av = *(const float4*)Ap;
        As[(aCol + 0) * BM + aRow] = av.x;
        As[(aCol + 1) * BM + aRow] = av.y;
        As[(aCol + 2) * BM + aRow] = av.z;
        As[(aCol + 3) * BM + aRow] = av.w;
        *(float4*)&Bs[bRow * BN + bCol] = *(const float4*)Wp;
        __syncthreads();
        Ap += BKK;
        Wp += (size_t)BKK * N;

#pragma unroll
        for (int k = 0; k < BKK; k++) {
            float4 a0 = *(const float4*)&As[k * BM + ty * TM];
            float4 a1 = *(const float4*)&As[k * BM + ty * TM + 4];
            float4 b0 = *(const float4*)&Bs[k * BN + tx * TN];
            float4 b1 = *(const float4*)&Bs[k * BN + tx * TN + 4];
            float a[TM] = {a0.x, a0.y, a0.z, a0.w, a1.x, a1.y, a1.z, a1.w};
            float b[TN] = {b0.x, b0.y, b0.z, b0.w, b1.x, b1.y, b1.z, b1.w};
#pragma unroll
            for (int i = 0; i < TM; i++)
#pragma unroll
                for (int j = 0; j < TN; j++)
                    acc[i][j] += a[i] * b[j];
        }
        __syncthreads();
    }

    float bv[TN];
#pragma unroll
    for (int j = 0; j < TN; j++) bv[j] = bias[col0 + tx * TN + j];

#pragma unroll
    for (int i = 0; i < TM; i++) {
        float4 o0, o1;
        o0.x = (acc[i][0] + bv[0]) * scale;
        o0.y = (acc[i][1] + bv[1]) * scale;
        o0.z = (acc[i][2] + bv[2]) * scale;
        o0.w = (acc[i][3] + bv[3]) * scale;
        o1.x = (acc[i][4] + bv[4]) * scale;
        o1.y = (acc[i][5] + bv[5]) * scale;
        o1.z = (acc[i][6] + bv[6]) * scale;
        o1.w = (acc[i][7] + bv[7]) * scale;
        float* cp = C + (size_t)(row0 + ty * TM + i) * N + col0 + tx * TN;
        *(float4*)cp       = o0;
        *(float4*)(cp + 4) = o1;
    }
}

// ---------------------------------------------------------------------------
// Flash attention: one block per (b,h, 64-query tile). DK=64, key tiles of 64.
// Q already pre-scaled by 1/sqrt(DK). 48KB static smem exactly.
// Thread mapping: t = ty*8 + tx ; owns rows {ty, ty+32}, cols tx*8..tx*8+7.
// ---------------------------------------------------------------------------
#define BQ 64
#define BKT 64

__global__ __launch_bounds__(256) void attn_kernel(
    const float* __restrict__ Qm, const float* __restrict__ Km,
    const float* __restrict__ Vm, float* __restrict__ Om)
{
    __shared__ float Qs[64 * 64];    // [dk][r]  (transposed)
    __shared__ float KVs[64 * 64];   // K phase: [dk][c] ; V phase: [c][dk]
    __shared__ float Ps[64 * 64];    // [c][r]

    const int t  = threadIdx.x;
    const int tx = t & 7;            // col group (8 cols each)
    const int ty = t >> 3;           // 0..31 -> rows ty, ty+32
    const int bh = blockIdx.x;       // 0..31
    const int b  = bh >> 4;
    const int h  = bh & 15;
    const int q0 = blockIdx.y * BQ;

    const float* Qg = Qm + (size_t)(b * Ss + q0) * Dd + h * DKh;
    const float* Kg = Km + (size_t)(b * Ss) * Dd + h * DKh;
    const float* Vg = Vm + (size_t)(b * Ss) * Dd + h * DKh;

    // Load Q tile transposed into smem: Qs[dk][r]
    {
        const int lr  = t >> 2;          // 0..63 (query row in tile)
        const int dk0 = (t & 3) * 16;
#pragma unroll
        for (int i = 0; i < 4; i++) {
            float4 v = *(const float4*)(Qg + (size_t)lr * Dd + dk0 + i * 4);
            Qs[(dk0 + i * 4 + 0) * 64 + lr] = v.x;
            Qs[(dk0 + i * 4 + 1) * 64 + lr] = v.y;
            Qs[(dk0 + i * 4 + 2) * 64 + lr] = v.z;
            Qs[(dk0 + i * 4 + 3) * 64 + lr] = v.w;
        }
    }

    float m0 = -INFINITY, m1 = -INFINITY;
    float l0 = 0.f, l1 = 0.f;
    float o0[8], o1[8];
#pragma unroll
    for (int j = 0; j < 8; j++) { o0[j] = 0.f; o1[j] = 0.f; }

    for (int kt = 0; kt < Ss; kt += BKT) {
        // Load K tile transposed: KVs[dk][c]
        {
            const int lr  = t >> 2;
            const int dk0 = (t & 3) * 16;
#pragma unroll
            for (int i = 0; i < 4; i++) {
                float4 v = *(const float4*)(Kg + (size_t)(kt + lr) * Dd + dk0 + i * 4);
                KVs[(dk0 + i * 4 + 0) * 64 + lr] = v.x;
                KVs[(dk0 + i * 4 + 1) * 64 + lr] = v.y;
                KVs[(dk0 + i * 4 + 2) * 64 + lr] = v.z;
                KVs[(dk0 + i * 4 + 3) * 64 + lr] = v.w;
            }
        }
        __syncthreads();   // also covers the Q load on first iteration

        // Scores: s[r][c] = sum_dk Q[r][dk] * K[c][dk]
        float s0[8], s1[8];
#pragma unroll
        for (int j = 0; j < 8; j++) { s0[j] = 0.f; s1[j] = 0.f; }
#pragma unroll 4
        for (int k = 0; k < 64; k++) {
            float qa = Qs[k * 64 + ty];
            float qb = Qs[k * 64 + ty + 32];
            float4 k0v = *(const float4*)&KVs[k * 64 + tx * 8];
            float4 k1v = *(const float4*)&KVs[k * 64 + tx * 8 + 4];
            float kv[8] = {k0v.x, k0v.y, k0v.z, k0v.w, k1v.x, k1v.y, k1v.z, k1v.w};
#pragma unroll
            for (int j = 0; j < 8; j++) {
                s0[j] += qa * kv[j];
                s1[j] += qb * kv[j];
            }
        }

        // Online softmax (row reduction over the 8 threads of each row)
        float mt0 = s0[0], mt1 = s1[0];
#pragma unroll
        for (int j = 1; j < 8; j++) { mt0 = fmaxf(mt0, s0[j]); mt1 = fmaxf(mt1, s1[j]); }
#pragma unroll
        for (int off = 1; off < 8; off <<= 1) {
            mt0 = fmaxf(mt0, __shfl_xor_sync(0xffffffffu, mt0, off));
            mt1 = fmaxf(mt1, __shfl_xor_sync(0xffffffffu, mt1, off));
        }
        float mn0 = fmaxf(m0, mt0), mn1 = fmaxf(m1, mt1);
        float c0 = __expf(m0 - mn0), c1 = __expf(m1 - mn1);

        float sum0 = 0.f, sum1 = 0.f;
#pragma unroll
        for (int j = 0; j < 8; j++) {
            float p0 = __expf(s0[j] - mn0);
            float p1 = __expf(s1[j] - mn1);
            sum0 += p0; sum1 += p1;
            Ps[(tx * 8 + j) * 64 + ty]      = p0;
            Ps[(tx * 8 + j) * 64 + ty + 32] = p1;
        }
#pragma unroll
        for (int off = 1; off < 8; off <<= 1) {
            sum0 += __shfl_xor_sync(0xffffffffu, sum0, off);
            sum1 += __shfl_xor_sync(0xffffffffu, sum1, off);
        }
        l0 = l0 * c0 + sum0;
        l1 = l1 * c1 + sum1;
        m0 = mn0; m1 = mn1;
#pragma unroll
        for (int j = 0; j < 8; j++) { o0[j] *= c0; o1[j] *= c1; }

        __syncthreads();   // Ks reads done, Ps writes visible

        // Load V tile natural: KVs[c][dk]
        {
            const int lr  = t >> 2;
            const int dk0 = (t & 3) * 16;
#pragma unroll
            for (int i = 0; i < 4; i++)
                *(float4*)&KVs[lr * 64 + dk0 + i * 4] =
                    *(const float4*)(Vg + (size_t)(kt + lr) * Dd + dk0 + i * 4);
        }
        __syncthreads();

        // O += P * V
#pragma unroll 4
        for (int c = 0; c < 64; c++) {
            float p0 = Ps[c * 64 + ty];
            float p1 = Ps[c * 64 + ty + 32];
            float4 v0 = *(const float4*)&KVs[c * 64 + tx * 8];
            float4 v1 = *(const float4*)&KVs[c * 64 + tx * 8 + 4];
            float vv[8] = {v0.x, v0.y, v0.z, v0.w, v1.x, v1.y, v1.z, v1.w};
#pragma unroll
            for (int j = 0; j < 8; j++) {
                o0[j] += p0 * vv[j];
                o1[j] += p1 * vv[j];
            }
        }
        __syncthreads();   // done with Vs/Ps before next tile overwrites
    }

    // Finalize and write to concat layout [B,S,D]
    float r0 = 1.f / l0, r1 = 1.f / l1;
    float* Og = Om + (size_t)(b * Ss + q0) * Dd + h * DKh;
    float4 w;
    w.x = o0[0] * r0; w.y = o0[1] * r0; w.z = o0[2] * r0; w.w = o0[3] * r0;
    *(float4*)(Og + (size_t)ty * Dd + tx * 8) = w;
    w.x = o0[4] * r0; w.y = o0[5] * r0; w.z = o0[6] * r0; w.w = o0[7] * r0;
    *(float4*)(Og + (size_t)ty * Dd + tx * 8 + 4) = w;
    w.x = o1[0] * r1; w.y = o1[1] * r1; w.z = o1[2] * r1; w.w = o1[3] * r1;
    *(float4*)(Og + (size_t)(ty + 32) * Dd + tx * 8) = w;
    w.x = o1[4] * r1; w.y = o1[5] * r1; w.z = o1[6] * r1; w.w = o1[7] * r1;
    *(float4*)(Og + (size_t)(ty + 32) * Dd + tx * 8 + 4) = w;
}

// ---------------------------------------------------------------------------
// Launch
// ---------------------------------------------------------------------------
extern "C" void kernel_launch(void* const* d_in, const int* in_sizes, int n_in,
                              void* d_out, int out_size)
{
    const float* x  = (const float*)d_in[0];
    const float* Wq = (const float*)d_in[1];
    const float* bq = (const float*)d_in[2];
    const float* Wk = (const float*)d_in[3];
    const float* bk = (const float*)d_in[4];
    const float* Wv = (const float*)d_in[5];
    const float* bv = (const float*)d_in[6];
    const float* Wo = (const float*)d_in[7];
    const float* bo = (const float*)d_in[8];
    float* out = (float*)d_out;

    float *q, *k, *v, *o;
    cudaGetSymbolAddress((void**)&q, g_q);
    cudaGetSymbolAddress((void**)&k, g_k);
    cudaGetSymbolAddress((void**)&v, g_v);
    cudaGetSymbolAddress((void**)&o, g_o);

    dim3 gGrid(Dd / BN, Mtot / BM);   // (8, 32)
    const float qscale = 0.125f;      // 1/sqrt(DK), folded into Q (incl. bias)

    sgemm_bias<<<gGrid, 256>>>(x, Wq, bq, q, Mtot, Dd, Dd, qscale);
    sgemm_bias<<<gGrid, 256>>>(x, Wk, bk, k, Mtot, Dd, Dd, 1.0f);
    sgemm_bias<<<gGrid, 256>>>(x, Wv, bv, v, Mtot, Dd, Dd, 1.0f);

    attn_kernel<<<dim3(Bb * Hh, Ss / BQ), 256>>>(q, k, v, o);

    sgemm_bias<<<gGrid, 256>>>(o, Wo, bo, out, Mtot, Dd, Dd, 1.0f);
}